// round 8
// baseline (speedup 1.0000x reference)
#include <cuda_runtime.h>

// out[b, o, f] = sum_t x[b, t, f] * W[f, o, t] + bias[f, o],  f < TGT=2
// x: (4096, 24, 256) f32   W: (256, 24, 24) f32   bias: (256, 24) f32
// out: (4096, 24, 2) f32 -> float2 out2[b*24 + o]
//
// Barrier-free, smem-free: one thread per (b,o) pair. 24 independent
// LDG.64 x-loads per thread (warp-broadcast dedup across the 24 lanes
// sharing b), W held in registers via 12 LDG.128 from the L1-hot 4.6KB
// slice. __launch_bounds__(128,1) removes the register cap that
// serialized these loads in the earlier attempt (regs must come out
// ~100+, not 32).

#define B_DIM 4096
#define T_DIM 24
#define F_DIM 256
#define O_DIM 24
#define NPAIR (B_DIM * O_DIM)        // 98304 threads
#define BLOCK 128

__global__ __launch_bounds__(BLOCK, 1) void dlinear_kernel(
    const float* __restrict__ x,
    const float* __restrict__ W,
    const float* __restrict__ bias,
    float2* __restrict__ out2)
{
    const int i = blockIdx.x * BLOCK + threadIdx.x;   // (b,o) pair
    const int b = i / O_DIM;
    const int o = i - b * O_DIM;

    // ---- 24 independent x loads, issued first (longest latency).
    // Lanes sharing b read identical addresses -> broadcast dedup.
    const float2* __restrict__ x2 =
        (const float2*)x + (size_t)b * T_DIM * (F_DIM / 2);
    float2 xv[T_DIM];
    #pragma unroll
    for (int t = 0; t < T_DIM; t++)
        xv[t] = __ldg(x2 + t * (F_DIM / 2));

    // ---- W rows for this o: 6 + 6 LDG.128 from L1-hot region.
    // W[0,o,:] at floats [o*24 .. o*24+23]  (24 % 4 == 0 -> float4-aligned)
    const float4* __restrict__ W0q = (const float4*)(W + o * T_DIM);
    const float4* __restrict__ W1q = (const float4*)(W + O_DIM * T_DIM + o * T_DIM);
    float4 w0[T_DIM / 4], w1[T_DIM / 4];
    #pragma unroll
    for (int j = 0; j < T_DIM / 4; j++) { w0[j] = __ldg(W0q + j); w1[j] = __ldg(W1q + j); }

    float2 acc = make_float2(__ldg(bias + o), __ldg(bias + O_DIM + o));

    const float* w0f = (const float*)w0;
    const float* w1f = (const float*)w1;
    #pragma unroll
    for (int t = 0; t < T_DIM; t++) {
        acc.x = fmaf(xv[t].x, w0f[t], acc.x);
        acc.y = fmaf(xv[t].y, w1f[t], acc.y);
    }

    out2[i] = acc;   // coalesced STG.64
}

extern "C" void kernel_launch(void* const* d_in, const int* in_sizes, int n_in,
                              void* d_out, int out_size)
{
    const float* x    = (const float*)d_in[0];
    const float* W    = (const float*)d_in[1];
    const float* bias = (const float*)d_in[2];
    float2* out2 = (float2*)d_out;

    dlinear_kernel<<<NPAIR / BLOCK, BLOCK>>>(x, W, bias, out2);   // 768 blocks
}

// round 9
// speedup vs baseline: 1.3478x; 1.3478x over previous
#include <cuda_runtime.h>
#include <cstdint>

// out[b, o, f] = sum_t x[b, t, f] * W[f, o, t] + bias[f, o],  f < TGT=2
// x: (4096, 24, 256) f32   W: (256, 24, 24) f32   bias: (256, 24) f32
// out: (4096, 24, 2) f32 -> float2 out2[b*24 + o]

#define B_DIM 4096
#define T_DIM 24
#define F_DIM 256
#define O_DIM 24
#define NB    8                       // batch rows per block
#define BLOCK 192                     // == NB*T_DIM (1 gather/thread) == NB*O_DIM (1 float2 out/thread)
#define GRID  (B_DIM / NB)            // 512 blocks
#define WJ    12                      // 24 (w0,w1) pairs = 12 float4 per o
#define WPAD  13                      // pad stride -> conflict-free LDS.128

__device__ __forceinline__ uint32_t smem_u32(const void* p) {
    return (uint32_t)__cvta_generic_to_shared(p);
}

__global__ __launch_bounds__(BLOCK) void dlinear_kernel(
    const float* __restrict__ x,
    const float* __restrict__ W,
    const float* __restrict__ bias,
    float2* __restrict__ out2)
{
    __shared__ float2 xs[NB * T_DIM];      // xs[b_l*24+t] = (x_f0, x_f1)
    __shared__ float4 Wq[O_DIM * WPAD];    // Wq[o*13+j] = (W0[2j],W1[2j],W0[2j+1],W1[2j+1])

    const int tid = threadIdx.x;
    const int b0  = blockIdx.x * NB;

    // ---- Phase 1a: x gather via cp.async 8B — GMEM->SMEM direct, no register
    // round-trip, one instruction per thread, every lane a distinct 128B line.
    {
        int b_l = tid / T_DIM;
        int t   = tid - b_l * T_DIM;
        const float2* gsrc = (const float2*)x
                           + (size_t)((b0 + b_l) * T_DIM + t) * (F_DIM / 2);
        uint32_t dst = smem_u32(&xs[tid]);
        asm volatile("cp.async.ca.shared.global [%0], [%1], 8;\n"
                     :: "r"(dst), "l"(gsrc) : "memory");
        asm volatile("cp.async.commit_group;\n" ::: "memory");
    }

    // ---- Phase 1b (overlapped with in-flight cp.async): stage W transposed.
    // t-pairs contiguous in native (f,o,t) layout -> 2 LDG.64 per float4.
    {
        const float2* __restrict__ W0 = (const float2*)W;                    // W[0,:,:]
        const float2* __restrict__ W1 = (const float2*)(W + O_DIM * T_DIM);  // W[1,:,:]
        #pragma unroll
        for (int j = tid; j < O_DIM * WJ; j += BLOCK) {
            int o  = j / WJ;
            int jj = j - o * WJ;
            float2 a = W0[o * WJ + jj];
            float2 c = W1[o * WJ + jj];
            Wq[o * WPAD + jj] = make_float4(a.x, c.x, a.y, c.y);
        }
    }

    asm volatile("cp.async.wait_group 0;\n" ::: "memory");
    __syncthreads();

    // ---- Phase 2: one float2 output per thread; 12+12 LDS.128 + 48 FMA.
    const int b_l = tid / O_DIM;
    const int o   = tid - b_l * O_DIM;

    const float4* __restrict__ xq = (const float4*)(xs + b_l * T_DIM);  // warp-broadcast
    const float4* __restrict__ wq = Wq + o * WPAD;                      // conflict-free

    float2 acc = make_float2(__ldg(bias + o), __ldg(bias + O_DIM + o));
    #pragma unroll
    for (int j = 0; j < WJ; j++) {
        float4 xv = xq[j];
        float4 wv = wq[j];
        acc.x = fmaf(xv.x, wv.x, acc.x);
        acc.y = fmaf(xv.y, wv.y, acc.y);
        acc.x = fmaf(xv.z, wv.z, acc.x);
        acc.y = fmaf(xv.w, wv.w, acc.y);
    }

    out2[(size_t)b0 * O_DIM + tid] = acc;   // coalesced STG.64
}

extern "C" void kernel_launch(void* const* d_in, const int* in_sizes, int n_in,
                              void* d_out, int out_size)
{
    const float* x    = (const float*)d_in[0];
    const float* W    = (const float*)d_in[1];
    const float* bias = (const float*)d_in[2];
    float2* out2 = (float2*)d_out;

    dlinear_kernel<<<GRID, BLOCK>>>(x, W, bias, out2);
}